// round 13
// baseline (speedup 1.0000x reference)
#include <cuda_runtime.h>
#include <cuda_bf16.h>
#include <math.h>
#include <stdint.h>

// Problem constants
#define S 2048
#define D 1024
#define E 8
#define M 4096
#define NSLOT (2*S)

// ---------------- device scratch (bf16 hi/lo planes) ----------------
__device__ __nv_bfloat16 g_x_hi[(size_t)S * D];
__device__ __nv_bfloat16 g_x_lo[(size_t)S * D];
__device__ __nv_bfloat16 g_Wgt_hi[(size_t)E * M * D];   // [e][n=M][k=D]
__device__ __nv_bfloat16 g_Wgt_lo[(size_t)E * M * D];
__device__ __nv_bfloat16 g_W1t_hi[(size_t)E * M * D];
__device__ __nv_bfloat16 g_W1t_lo[(size_t)E * M * D];
__device__ __nv_bfloat16 g_W2t_hi[(size_t)E * D * M];   // [e][n=D][k=M]
__device__ __nv_bfloat16 g_W2t_lo[(size_t)E * D * M];
__device__ __nv_bfloat16 g_H_hi[(size_t)NSLOT * M];
__device__ __nv_bfloat16 g_H_lo[(size_t)NSLOT * M];
__device__ int   g_cnt[E];
__device__ int   g_off[E + 1];
__device__ int   g_pos[E];
__device__ int   g_slot_tok[NSLOT];
__device__ float g_slot_w[NSLOT];
__device__ int   g_tok_e[S * 2];
__device__ float g_tok_w[S * 2];

// ---------------- helpers ----------------
__device__ __forceinline__ uint32_t smem_u32(const void* p) {
    uint32_t a;
    asm("{ .reg .u64 t; cvta.to.shared.u64 t, %1; cvt.u32.u64 %0, t; }" : "=r"(a) : "l"(p));
    return a;
}

#define LDSM4(r0, r1, r2, r3, addr) \
    asm volatile("ldmatrix.sync.aligned.m8n8.x4.shared.b16 {%0,%1,%2,%3}, [%4];" \
        : "=r"(r0), "=r"(r1), "=r"(r2), "=r"(r3) : "r"(addr))

#define MMA16816(c, a0, a1, a2, a3, b0, b1) \
    asm volatile("mma.sync.aligned.m16n8k16.row.col.f32.bf16.bf16.f32 " \
        "{%0,%1,%2,%3}, {%4,%5,%6,%7}, {%8,%9}, {%0,%1,%2,%3};" \
        : "+f"((c)[0]), "+f"((c)[1]), "+f"((c)[2]), "+f"((c)[3]) \
        : "r"(a0), "r"(a1), "r"(a2), "r"(a3), "r"(b0), "r"(b1))

// Plain 16B cp.async
__device__ __forceinline__ void cpa16(uint32_t dst, const void* src) {
    asm volatile("cp.async.cg.shared.global [%0], [%1], 16;"
                 :: "r"(dst), "l"(src));
}
#define CPCOMMIT() asm volatile("cp.async.commit_group;")
#define CPWAIT1()  asm volatile("cp.async.wait_group 1;")
#define CPWAIT0()  asm volatile("cp.async.wait_group 0;")

// Split fp32 pair -> packed bf16x2 hi and lo
__device__ __forceinline__ void split2(float a, float b, uint32_t& hi, uint32_t& lo) {
    __nv_bfloat16 ah = __float2bfloat16(a);
    __nv_bfloat16 bh = __float2bfloat16(b);
    __nv_bfloat162 h2; h2.x = ah; h2.y = bh;
    __nv_bfloat162 l2 = __floats2bfloat162_rn(a - __bfloat162float(ah),
                                              b - __bfloat162float(bh));
    hi = *(uint32_t*)&h2;
    lo = *(uint32_t*)&l2;
}

// ---------------- kernel 0: zero output + counters ----------------
__global__ void k_init(float* out) {
    int t = blockIdx.x * blockDim.x + threadIdx.x;
    if (t < S * D) out[t] = 0.0f;
    if (t < E) g_cnt[t] = 0;
}

// ---------------- kernel 1: gating (1 warp / token) ----------------
__global__ void k_gate(const float* __restrict__ x,
                       const float* __restrict__ Wgate,
                       const float* __restrict__ bgate) {
    int warp = (blockIdx.x * blockDim.x + threadIdx.x) >> 5;
    int lane = threadIdx.x & 31;
    if (warp >= S) return;
    const float* xr = x + (size_t)warp * D;
    float acc[E];
#pragma unroll
    for (int e = 0; e < E; e++) acc[e] = 0.0f;
    for (int d = lane; d < D; d += 32) {
        float xv = xr[d];
        const float* wr = Wgate + d * E;
#pragma unroll
        for (int e = 0; e < E; e++) acc[e] += xv * wr[e];
    }
#pragma unroll
    for (int e = 0; e < E; e++) {
#pragma unroll
        for (int o = 16; o > 0; o >>= 1)
            acc[e] += __shfl_down_sync(0xffffffffu, acc[e], o);
    }
    if (lane == 0) {
        float l[E];
        float mx = -1e30f;
#pragma unroll
        for (int e = 0; e < E; e++) { l[e] = acc[e] + bgate[e]; mx = fmaxf(mx, l[e]); }
        float ex[E];
#pragma unroll
        for (int e = 0; e < E; e++) ex[e] = expf(l[e] - mx);
        int i0 = 0;
#pragma unroll
        for (int e = 1; e < E; e++) if (ex[e] > ex[i0]) i0 = e;
        int i1 = (i0 == 0) ? 1 : 0;
#pragma unroll
        for (int e = 0; e < E; e++) if (e != i0 && ex[e] > ex[i1]) i1 = e;
        float w0 = ex[i0], w1 = ex[i1];
        float inv = 1.0f / (w0 + w1);
        w0 *= inv; w1 *= inv;
        g_tok_e[warp * 2 + 0] = i0; g_tok_w[warp * 2 + 0] = w0;
        g_tok_e[warp * 2 + 1] = i1; g_tok_w[warp * 2 + 1] = w1;
        atomicAdd(&g_cnt[i0], 1);
        atomicAdd(&g_cnt[i1], 1);
    }
}

// ---------------- kernel 2: prefix offsets ----------------
__global__ void k_offsets() {
    if (threadIdx.x == 0) {
        int acc = 0;
        g_off[0] = 0;
        for (int e = 0; e < E; e++) {
            acc += g_cnt[e];
            g_off[e + 1] = acc;
            g_pos[e] = g_off[e];
        }
    }
}

// ---------------- kernel 3: scatter ----------------
__global__ void k_scatter() {
    int t = blockIdx.x * blockDim.x + threadIdx.x;
    if (t >= S) return;
#pragma unroll
    for (int k = 0; k < 2; k++) {
        int e = g_tok_e[t * 2 + k];
        int p = atomicAdd(&g_pos[e], 1);
        g_slot_tok[p] = t;
        g_slot_w[p] = g_tok_w[t * 2 + k];
    }
}

// ---------------- prep: split x ----------------
__global__ void k_xsplit(const float* __restrict__ x) {
    int i = blockIdx.x * blockDim.x + threadIdx.x;
    if (i >= S * D / 2) return;
    float2 v = ((const float2*)x)[i];
    uint32_t h, l;
    split2(v.x, v.y, h, l);
    ((uint32_t*)g_x_hi)[i] = h;
    ((uint32_t*)g_x_lo)[i] = l;
}

// ---------------- prep: transpose + split weights  in[K][N] -> out[N][K] ----------
// Output plane selected IN DEVICE CODE (host-side __device__ symbol args are the
// host shadow address — the R7-R9 silent-zero bug). Coalesced u32 (bf16x2) writes.
__global__ void k_tsplit(const float* __restrict__ in, int which, int K, int N) {
    __nv_bfloat16 *oh, *ol;
    if (which == 0)      { oh = g_Wgt_hi; ol = g_Wgt_lo; }
    else if (which == 1) { oh = g_W1t_hi; ol = g_W1t_lo; }
    else                 { oh = g_W2t_hi; ol = g_W2t_lo; }
    __shared__ float t[64][33];
    const size_t eo = (size_t)blockIdx.z * K * N;
    in += eo;
    uint32_t* ohu = (uint32_t*)(oh + eo);
    uint32_t* olu = (uint32_t*)(ol + eo);
    int n0 = blockIdx.x * 32, k0 = blockIdx.y * 64;
    int tx = threadIdx.x, ty = threadIdx.y;   // (32, 8)
#pragma unroll
    for (int i = 0; i < 8; i++) {
        int kl = ty + 8 * i;
        t[kl][tx] = in[(size_t)(k0 + kl) * N + n0 + tx];
    }
    __syncthreads();
#pragma unroll
    for (int i = 0; i < 4; i++) {
        int nl = ty + 8 * i;
        float v0 = t[2 * tx][nl];
        float v1 = t[2 * tx + 1][nl];
        uint32_t h, l;
        split2(v0, v1, h, l);
        size_t o = ((size_t)(n0 + nl) * K + k0) / 2 + tx;
        ohu[o] = h;
        olu[o] = l;
    }
}

// ---------------- GEMM tiling ----------------
#define AS 40                        // smem row stride, bf16 elems (80 B)
#define ROWB (AS * 2)                // 80
#define PLANEB (128 * ROWB)          // 10240 bytes per 128x32 plane
#define NSTG 3                       // 3-stage ring: no write-after-read hazard,
                                     // single __syncthreads per iteration

// ff1: stage = 6 planes (A hi/lo, G hi/lo, U hi/lo)
#define F1_STG  (6 * PLANEB)         // 61440
#define F1_SMEM (NSTG * F1_STG + 512)  // 184832

__device__ __forceinline__ void ff1_load(uint32_t sb, int stage, int k0,
                                         int tid, const int* s_tok,
                                         int e, int col0) {
    uint32_t st = sb + stage * F1_STG;
    int ch = tid & 3;
    // A: x hi/lo gathered rows (invalid rows clamped to token 0; discarded in epilogue)
#pragma unroll
    for (int p = 0; p < 4; p++) {
        int r = (((p & 1) << 8) + tid) >> 2;
        const __nv_bfloat16* xs = (p >> 1) ? g_x_lo : g_x_hi;
        int tok = s_tok[r];
        if (tok < 0) tok = 0;
        const void* src = xs + (size_t)tok * D + k0 + ch * 8;
        cpa16(st + (p >> 1) * PLANEB + r * ROWB + ch * 16, src);
    }
    // B: Wg/W1 transposed planes [n][k]
#pragma unroll
    for (int p = 0; p < 8; p++) {
        int r = (((p & 1) << 8) + tid) >> 2;
        const __nv_bfloat16* ws = (p >> 1) == 0 ? g_Wgt_hi
                                : (p >> 1) == 1 ? g_Wgt_lo
                                : (p >> 1) == 2 ? g_W1t_hi : g_W1t_lo;
        const void* src = ws + ((size_t)e * M + col0 + r) * (size_t)D + k0 + ch * 8;
        cpa16(st + (2 + (p >> 1)) * PLANEB + r * ROWB + ch * 16, src);
    }
}

// ---------------- kernel 4: ff1  H = swish(X@Wg+bg) * (X@W1+b1) ----------------
__global__ void __launch_bounds__(256)
k_ff1(const float* __restrict__ bg, const float* __restrict__ b1) {
    extern __shared__ char smem[];
    const int e = blockIdx.z;
    const int base = g_off[e];
    const int cnt = g_off[e + 1] - base;
    const int row0 = blockIdx.x * 128;
    if (row0 >= cnt) return;
    const int col0 = blockIdx.y * 128;
    const int tid = threadIdx.x;
    const int wid = tid >> 5, lane = tid & 31;
    const int warp_m = wid >> 2, warp_n = wid & 3;
    const uint32_t sb = smem_u32(smem);

    int* s_tok = (int*)(smem + NSTG * F1_STG);
    if (tid < 128) {
        int gr = row0 + tid;
        s_tok[tid] = (gr < cnt) ? g_slot_tok[base + gr] : -1;
    }
    __syncthreads();

    const uint32_t a_rel = (uint32_t)(((warp_m * 64 + (lane & 15)) * AS + (lane >> 4) * 8) * 2);
    const uint32_t b_rel = (uint32_t)(((warp_n * 32 + (lane & 7) + ((lane >> 4) * 8)) * AS
                                      + ((lane >> 3) & 1) * 8) * 2);

    float cg[4][4][4], cu[4][4][4];
#pragma unroll
    for (int i = 0; i < 4; i++)
#pragma unroll
        for (int j = 0; j < 4; j++)
#pragma unroll
            for (int q = 0; q < 4; q++) { cg[i][j][q] = 0.0f; cu[i][j][q] = 0.0f; }

    const int NIT = D / 32;   // 32
    ff1_load(sb, 0, 0, tid, s_tok, e, col0);
    CPCOMMIT();
    ff1_load(sb, 1, 32, tid, s_tok, e, col0);
    CPCOMMIT();

    int stage = 0, nstage = 2;
    for (int it = 0; it < NIT; it++) {
        if (it < NIT - 1) { CPWAIT1(); } else { CPWAIT0(); }
        __syncthreads();
        // prefetch chunk it+2 into the free stage (read 2 iters ago; sync above
        // guarantees all warps are past that compute)
        if (it + 2 < NIT) {
            ff1_load(sb, nstage, (it + 2) * 32, tid, s_tok, e, col0);
            CPCOMMIT();
        }
        uint32_t st = sb + stage * F1_STG;
#pragma unroll
        for (int ks = 0; ks < 2; ks++) {
            const uint32_t kso = (uint32_t)(ks * 32);
            uint32_t ah[4][4], al[4][4];
#pragma unroll
            for (int mt = 0; mt < 4; mt++) {
                uint32_t ad = st + a_rel + (uint32_t)(mt * 16 * ROWB) + kso;
                LDSM4(ah[mt][0], ah[mt][1], ah[mt][2], ah[mt][3], ad);
                LDSM4(al[mt][0], al[mt][1], al[mt][2], al[mt][3], ad + PLANEB);
            }
            uint32_t bgh[4][2], bgl[4][2], buh[4][2], bul[4][2];
#pragma unroll
            for (int nt2 = 0; nt2 < 2; nt2++) {
                uint32_t bd = st + b_rel + (uint32_t)(nt2 * 16 * ROWB) + kso;
                LDSM4(bgh[2*nt2][0], bgh[2*nt2][1], bgh[2*nt2+1][0], bgh[2*nt2+1][1], bd + 2 * PLANEB);
                LDSM4(bgl[2*nt2][0], bgl[2*nt2][1], bgl[2*nt2+1][0], bgl[2*nt2+1][1], bd + 3 * PLANEB);
                LDSM4(buh[2*nt2][0], buh[2*nt2][1], buh[2*nt2+1][0], buh[2*nt2+1][1], bd + 4 * PLANEB);
                LDSM4(bul[2*nt2][0], bul[2*nt2][1], bul[2*nt2+1][0], bul[2*nt2+1][1], bd + 5 * PLANEB);
            }
#pragma unroll
            for (int mt = 0; mt < 4; mt++) {
#pragma unroll
                for (int nt = 0; nt < 4; nt++) {
                    MMA16816(cg[mt][nt], ah[mt][0], ah[mt][1], ah[mt][2], ah[mt][3], bgh[nt][0], bgh[nt][1]);
                    MMA16816(cg[mt][nt], ah[mt][0], ah[mt][1], ah[mt][2], ah[mt][3], bgl[nt][0], bgl[nt][1]);
                    MMA16816(cg[mt][nt], al[mt][0], al[mt][1], al[mt][2], al[mt][3], bgh[nt][0], bgh[nt][1]);
                    MMA16816(cu[mt][nt], ah[mt][0], ah[mt][1], ah[mt][2], ah[mt][3], buh[nt][0], buh[nt][1]);
                    MMA16816(cu[mt][nt], ah[mt][0], ah[mt][1], ah[mt][2], ah[mt][3], bul[nt][0], bul[nt][1]);
                    MMA16816(cu[mt][nt], al[mt][0], al[mt][1], al[mt][2], al[mt][3], buh[nt][0], buh[nt][1]);
                }
            }
        }
        stage = (stage + 1 == NSTG) ? 0 : stage + 1;
        nstage = (nstage + 1 == NSTG) ? 0 : nstage + 1;
    }

    // ---- epilogue: swish-gate, write H as bf16 hi/lo pairs ----
    const float* bg_e = bg + e * M;
    const float* b1_e = b1 + e * M;
    uint32_t* Hh32 = (uint32_t*)g_H_hi;
    uint32_t* Hl32 = (uint32_t*)g_H_lo;
#pragma unroll
    for (int mt = 0; mt < 4; mt++) {
#pragma unroll
        for (int nt = 0; nt < 4; nt++) {
            int r_base = row0 + warp_m * 64 + mt * 16 + (lane >> 2);
            int c = col0 + warp_n * 32 + nt * 8 + (lane & 3) * 2;
#pragma unroll
            for (int hh = 0; hh < 2; hh++) {
                int r = r_base + hh * 8;
                if (r < cnt) {
                    float a0 = cg[mt][nt][2*hh]   + bg_e[c];
                    float a1 = cg[mt][nt][2*hh+1] + bg_e[c + 1];
                    float u0 = cu[mt][nt][2*hh]   + b1_e[c];
                    float u1 = cu[mt][nt][2*hh+1] + b1_e[c + 1];
                    float h0 = (a0 / (1.0f + __expf(-a0))) * u0;
                    float h1 = (a1 / (1.0f + __expf(-a1))) * u1;
                    uint32_t hu, lu;
                    split2(h0, h1, hu, lu);
                    size_t o = ((size_t)(base + r) * M + c) >> 1;
                    Hh32[o] = hu;
                    Hl32[o] = lu;
                }
            }
        }
    }
}

// ff2: stage = 4 planes (A hi/lo, B hi/lo)
#define F2_STG  (4 * PLANEB)          // 40960
#define F2_SMEM (NSTG * F2_STG)       // 122880
#define SPLITK  4

__device__ __forceinline__ void ff2_load(uint32_t sb, int stage, int kabs,
                                         int tid, int base, int cnt,
                                         int row0, int e, int col0) {
    uint32_t st = sb + stage * F2_STG;
    int ch = tid & 3;
    // A: H hi/lo rows (invalid rows clamped; discarded in epilogue)
#pragma unroll
    for (int p = 0; p < 4; p++) {
        int r = (((p & 1) << 8) + tid) >> 2;
        const __nv_bfloat16* hs = (p >> 1) ? g_H_lo : g_H_hi;
        int gr = row0 + r;
        if (gr >= cnt) gr = cnt - 1;
        const void* src = hs + (size_t)(base + gr) * M + kabs + ch * 8;
        cpa16(st + (p >> 1) * PLANEB + r * ROWB + ch * 16, src);
    }
    // B: W2 transposed planes [n=D][k=M]
#pragma unroll
    for (int p = 0; p < 4; p++) {
        int r = (((p & 1) << 8) + tid) >> 2;
        const __nv_bfloat16* ws = (p >> 1) ? g_W2t_lo : g_W2t_hi;
        const void* src = ws + ((size_t)e * D + col0 + r) * (size_t)M + kabs + ch * 8;
        cpa16(st + (2 + (p >> 1)) * PLANEB + r * ROWB + ch * 16, src);
    }
}

// ---------------- kernel 5: ff2  Y = H@W2 + b2, weighted combine (split-K) ----
__global__ void __launch_bounds__(256)
k_ff2(const float* __restrict__ b2, float* __restrict__ out) {
    extern __shared__ char smem[];
    const int e = blockIdx.z >> 2;
    const int sk = blockIdx.z & 3;
    const int base = g_off[e];
    const int cnt = g_off[e + 1] - base;
    const int row0 = blockIdx.x * 128;
    if (row0 >= cnt) return;
    const int col0 = blockIdx.y * 128;
    const int kb = sk * (M / SPLITK);
    const int tid = threadIdx.x;
    const int wid = tid >> 5, lane = tid & 31;
    const int warp_m = wid >> 2, warp_n = wid & 3;
    const uint32_t sb = smem_u32(smem);

    const uint32_t a_rel = (uint32_t)(((warp_m * 64 + (lane & 15)) * AS + (lane >> 4) * 8) * 2);
    const uint32_t b_rel = (uint32_t)(((warp_n * 32 + (lane & 7) + ((lane >> 4) * 8)) * AS
                                      + ((lane >> 3) & 1) * 8) * 2);

    float cc[4][4][4];
#pragma unroll
    for (int i = 0; i < 4; i++)
#pragma unroll
        for (int j = 0; j < 4; j++)
#pragma unroll
            for (int q = 0; q < 4; q++) cc[i][j][q] = 0.0f;

    const int NIT = (M / SPLITK) / 32;   // 32
    ff2_load(sb, 0, kb, tid, base, cnt, row0, e, col0);
    CPCOMMIT();
    ff2_load(sb, 1, kb + 32, tid, base, cnt, row0, e, col0);
    CPCOMMIT();

    int stage = 0, nstage = 2;
    for (int it = 0; it < NIT; it++) {
        if (it < NIT - 1) { CPWAIT1(); } else { CPWAIT0(); }
        __syncthreads();
        if (it + 2 < NIT) {
            ff2_load(sb, nstage, kb + (it + 2) * 32, tid, base, cnt, row0, e, col0);
            CPCOMMIT();
        }
        uint32_t st = sb + stage * F2_STG;
#pragma unroll
        for (int ks = 0; ks < 2; ks++) {
            const uint32_t kso = (uint32_t)(ks * 32);
            uint32_t ah[4][4], al[4][4];
#pragma unroll
            for (int mt = 0; mt < 4; mt++) {
                uint32_t ad = st + a_rel + (uint32_t)(mt * 16 * ROWB) + kso;
                LDSM4(ah[mt][0], ah[mt][1], ah[mt][2], ah[mt][3], ad);
                LDSM4(al[mt][0], al[mt][1], al[mt][2], al[mt][3], ad + PLANEB);
            }
            uint32_t bh[4][2], bl[4][2];
#pragma unroll
            for (int nt2 = 0; nt2 < 2; nt2++) {
                uint32_t bd = st + b_rel + (uint32_t)(nt2 * 16 * ROWB) + kso;
                LDSM4(bh[2*nt2][0], bh[2*nt2][1], bh[2*nt2+1][0], bh[2*nt2+1][1], bd + 2 * PLANEB);
                LDSM4(bl[2*nt2][0], bl[2*nt2][1], bl[2*nt2+1][0], bl[2*nt2+1][1], bd + 3 * PLANEB);
            }
#pragma unroll
            for (int mt = 0; mt < 4; mt++) {
#pragma unroll
                for (int nt = 0; nt < 4; nt++) {
                    MMA16816(cc[mt][nt], ah[mt][0], ah[mt][1], ah[mt][2], ah[mt][3], bh[nt][0], bh[nt][1]);
                    MMA16816(cc[mt][nt], ah[mt][0], ah[mt][1], ah[mt][2], ah[mt][3], bl[nt][0], bl[nt][1]);
                    MMA16816(cc[mt][nt], al[mt][0], al[mt][1], al[mt][2], al[mt][3], bh[nt][0], bh[nt][1]);
                }
            }
        }
        stage = (stage + 1 == NSTG) ? 0 : stage + 1;
        nstage = (nstage + 1 == NSTG) ? 0 : nstage + 1;
    }

    // ---- epilogue: (bias on split 0) + weighted atomic combine ----
    const float* b2_e = b2 + e * D;
#pragma unroll
    for (int mt = 0; mt < 4; mt++) {
#pragma unroll
        for (int nt = 0; nt < 4; nt++) {
            int r_base = row0 + warp_m * 64 + mt * 16 + (lane >> 2);
            int c = col0 + warp_n * 32 + nt * 8 + (lane & 3) * 2;
            float bb0 = (sk == 0) ? b2_e[c]     : 0.0f;
            float bb1 = (sk == 0) ? b2_e[c + 1] : 0.0f;
#pragma unroll
            for (int hh = 0; hh < 2; hh++) {
                int r = r_base + hh * 8;
                if (r < cnt) {
                    int slot = base + r;
                    int tok = g_slot_tok[slot];
                    float w = g_slot_w[slot];
                    float y0 = cc[mt][nt][2*hh]   + bb0;
                    float y1 = cc[mt][nt][2*hh+1] + bb1;
                    float* op = out + (size_t)tok * D + c;
                    atomicAdd(op,     w * y0);
                    atomicAdd(op + 1, w * y1);
                }
            }
        }
    }
}

// ---------------- launch ----------------
extern "C" void kernel_launch(void* const* d_in, const int* in_sizes, int n_in,
                              void* d_out, int out_size) {
    const float* x     = (const float*)d_in[0];
    const float* Wgate = (const float*)d_in[1];
    const float* bgate = (const float*)d_in[2];
    const float* Wg    = (const float*)d_in[3];
    const float* bg    = (const float*)d_in[4];
    const float* W1    = (const float*)d_in[5];
    const float* b1    = (const float*)d_in[6];
    const float* W2    = (const float*)d_in[7];
    const float* b2    = (const float*)d_in[8];
    float* out = (float*)d_out;

    cudaFuncSetAttribute(k_ff1, cudaFuncAttributeMaxDynamicSharedMemorySize, F1_SMEM);
    cudaFuncSetAttribute(k_ff2, cudaFuncAttributeMaxDynamicSharedMemorySize, F2_SMEM);

    k_init<<<(S * D + 511) / 512, 512>>>(out);
    k_gate<<<S / 8, 256>>>(x, Wgate, bgate);
    k_offsets<<<1, 32>>>();
    k_scatter<<<(S + 255) / 256, 256>>>();

    // prep: bf16 hi/lo splits (+ weight transpose); plane selected device-side
    k_xsplit<<<(S * D / 2 + 255) / 256, 256>>>(x);
    dim3 tb(32, 8);
    k_tsplit<<<dim3(M / 32, D / 64, E), tb>>>(Wg, 0, D, M);
    k_tsplit<<<dim3(M / 32, D / 64, E), tb>>>(W1, 1, D, M);
    k_tsplit<<<dim3(D / 32, M / 64, E), tb>>>(W2, 2, M, D);

    dim3 g1(NSLOT / 128, M / 128, E);          // (32, 32, 8)
    k_ff1<<<g1, 256, F1_SMEM>>>(bg, b1);
    dim3 g2(NSLOT / 128, D / 128, E * SPLITK); // (32, 8, 32)
    k_ff2<<<g2, 256, F2_SMEM>>>(b2, out);
}

// round 14
// speedup vs baseline: 2.2590x; 2.2590x over previous
#include <cuda_runtime.h>
#include <cuda_fp16.h>
#include <math.h>
#include <stdint.h>

// Problem constants
#define S 2048
#define D 1024
#define E 8
#define M 4096
#define NSLOT (2*S)

// ---------------- device scratch (fp16 planes) ----------------
__device__ __half g_x16[(size_t)S * D];
__device__ __half g_Wgt[(size_t)E * M * D];   // [e][n=M][k=D]
__device__ __half g_W1t[(size_t)E * M * D];
__device__ __half g_W2t[(size_t)E * D * M];   // [e][n=D][k=M]
__device__ __half g_H[(size_t)NSLOT * M];
__device__ int   g_cnt[E];
__device__ int   g_off[E + 1];
__device__ int   g_pos[E];
__device__ int   g_slot_tok[NSLOT];
__device__ float g_slot_w[NSLOT];
__device__ int   g_tok_e[S * 2];
__device__ float g_tok_w[S * 2];

// ---------------- helpers ----------------
__device__ __forceinline__ uint32_t smem_u32(const void* p) {
    uint32_t a;
    asm("{ .reg .u64 t; cvta.to.shared.u64 t, %1; cvt.u32.u64 %0, t; }" : "=r"(a) : "l"(p));
    return a;
}

#define LDSM4(r0, r1, r2, r3, addr) \
    asm volatile("ldmatrix.sync.aligned.m8n8.x4.shared.b16 {%0,%1,%2,%3}, [%4];" \
        : "=r"(r0), "=r"(r1), "=r"(r2), "=r"(r3) : "r"(addr))

#define MMA16816(c, a0, a1, a2, a3, b0, b1) \
    asm volatile("mma.sync.aligned.m16n8k16.row.col.f32.f16.f16.f32 " \
        "{%0,%1,%2,%3}, {%4,%5,%6,%7}, {%8,%9}, {%0,%1,%2,%3};" \
        : "+f"((c)[0]), "+f"((c)[1]), "+f"((c)[2]), "+f"((c)[3]) \
        : "r"(a0), "r"(a1), "r"(a2), "r"(a3), "r"(b0), "r"(b1))

// Plain 16B cp.async
__device__ __forceinline__ void cpa16(uint32_t dst, const void* src) {
    asm volatile("cp.async.cg.shared.global [%0], [%1], 16;"
                 :: "r"(dst), "l"(src));
}
#define CPCOMMIT() asm volatile("cp.async.commit_group;")
#define CPWAIT1()  asm volatile("cp.async.wait_group 1;")
#define CPWAIT0()  asm volatile("cp.async.wait_group 0;")

// ---------------- kernel 0: zero output + counters ----------------
__global__ void k_init(float* out) {
    int t = blockIdx.x * blockDim.x + threadIdx.x;
    if (t < S * D) out[t] = 0.0f;
    if (t < E) g_cnt[t] = 0;
}

// ---------------- kernel 1: gating (1 warp / token, fp32) ----------------
__global__ void k_gate(const float* __restrict__ x,
                       const float* __restrict__ Wgate,
                       const float* __restrict__ bgate) {
    int warp = (blockIdx.x * blockDim.x + threadIdx.x) >> 5;
    int lane = threadIdx.x & 31;
    if (warp >= S) return;
    const float* xr = x + (size_t)warp * D;
    float acc[E];
#pragma unroll
    for (int e = 0; e < E; e++) acc[e] = 0.0f;
    for (int d = lane; d < D; d += 32) {
        float xv = xr[d];
        const float* wr = Wgate + d * E;
#pragma unroll
        for (int e = 0; e < E; e++) acc[e] += xv * wr[e];
    }
#pragma unroll
    for (int e = 0; e < E; e++) {
#pragma unroll
        for (int o = 16; o > 0; o >>= 1)
            acc[e] += __shfl_down_sync(0xffffffffu, acc[e], o);
    }
    if (lane == 0) {
        float l[E];
        float mx = -1e30f;
#pragma unroll
        for (int e = 0; e < E; e++) { l[e] = acc[e] + bgate[e]; mx = fmaxf(mx, l[e]); }
        float ex[E];
#pragma unroll
        for (int e = 0; e < E; e++) ex[e] = expf(l[e] - mx);
        int i0 = 0;
#pragma unroll
        for (int e = 1; e < E; e++) if (ex[e] > ex[i0]) i0 = e;
        int i1 = (i0 == 0) ? 1 : 0;
#pragma unroll
        for (int e = 0; e < E; e++) if (e != i0 && ex[e] > ex[i1]) i1 = e;
        float w0 = ex[i0], w1 = ex[i1];
        float inv = 1.0f / (w0 + w1);
        w0 *= inv; w1 *= inv;
        g_tok_e[warp * 2 + 0] = i0; g_tok_w[warp * 2 + 0] = w0;
        g_tok_e[warp * 2 + 1] = i1; g_tok_w[warp * 2 + 1] = w1;
        atomicAdd(&g_cnt[i0], 1);
        atomicAdd(&g_cnt[i1], 1);
    }
}

// ---------------- kernel 2: prefix offsets ----------------
__global__ void k_offsets() {
    if (threadIdx.x == 0) {
        int acc = 0;
        g_off[0] = 0;
        for (int e = 0; e < E; e++) {
            acc += g_cnt[e];
            g_off[e + 1] = acc;
            g_pos[e] = g_off[e];
        }
    }
}

// ---------------- kernel 3: scatter ----------------
__global__ void k_scatter() {
    int t = blockIdx.x * blockDim.x + threadIdx.x;
    if (t >= S) return;
#pragma unroll
    for (int k = 0; k < 2; k++) {
        int e = g_tok_e[t * 2 + k];
        int p = atomicAdd(&g_pos[e], 1);
        g_slot_tok[p] = t;
        g_slot_w[p] = g_tok_w[t * 2 + k];
    }
}

// ---------------- prep: convert x to fp16 ----------------
__global__ void k_xcvt(const float* __restrict__ x) {
    int i = blockIdx.x * blockDim.x + threadIdx.x;
    if (i >= S * D / 2) return;
    float2 v = ((const float2*)x)[i];
    __half2 h2 = __floats2half2_rn(v.x, v.y);
    ((uint32_t*)g_x16)[i] = *(uint32_t*)&h2;
}

// ---------------- prep: transpose + convert weights  in[K][N] -> out[N][K] ------
// Output plane selected IN DEVICE CODE (host-side __device__ symbol args are the
// host shadow address — silent-zero via ATS). Coalesced half2 writes.
__global__ void k_tcvt(const float* __restrict__ in, int which, int K, int N) {
    __half* o = (which == 0) ? g_Wgt : (which == 1) ? g_W1t : g_W2t;
    __shared__ float t[64][33];
    const size_t eo = (size_t)blockIdx.z * K * N;
    in += eo;
    uint32_t* ou = (uint32_t*)(o + eo);
    int n0 = blockIdx.x * 32, k0 = blockIdx.y * 64;
    int tx = threadIdx.x, ty = threadIdx.y;   // (32, 8)
#pragma unroll
    for (int i = 0; i < 8; i++) {
        int kl = ty + 8 * i;
        t[kl][tx] = in[(size_t)(k0 + kl) * N + n0 + tx];
    }
    __syncthreads();
#pragma unroll
    for (int i = 0; i < 4; i++) {
        int nl = ty + 8 * i;
        __half2 h2 = __floats2half2_rn(t[2 * tx][nl], t[2 * tx + 1][nl]);
        size_t oo = ((size_t)(n0 + nl) * K + k0) / 2 + tx;
        ou[oo] = *(uint32_t*)&h2;
    }
}

// ---------------- GEMM tiling ----------------
#define AS 72                        // smem row stride, fp16 elems (144 B)
#define ROWB (AS * 2)                // 144 (mod 128 = 16 -> conflict-free ldmatrix)
#define PLANEB (128 * ROWB)          // 18432 bytes per 128x64 plane

// ff1: stage = 3 planes (A, G, U), double buffered, K-chunk 64
#define F1_STG  (3 * PLANEB)         // 55296
#define F1_SMEM (2 * F1_STG + 512)   // 111104

__device__ __forceinline__ void ff1_load(uint32_t sb, int stage, int k0,
                                         int tid, const int* s_tok,
                                         int e, int col0) {
    uint32_t st = sb + stage * F1_STG;
    // A: gathered x rows, 1024 x 16B, 4 per thread
#pragma unroll
    for (int p = 0; p < 4; p++) {
        int idx = p * 256 + tid;
        int r = idx >> 3, c = idx & 7;
        int tok = s_tok[r];
        if (tok < 0) tok = 0;
        const void* src = g_x16 + (size_t)tok * D + k0 + c * 8;
        cpa16(st + r * ROWB + c * 16, src);
    }
    // B: Wg / W1 transposed planes [n][k]
#pragma unroll
    for (int p = 0; p < 8; p++) {
        int idx = (p & 3) * 256 + tid;
        int r = idx >> 3, c = idx & 7;
        const __half* ws = (p >> 2) ? g_W1t : g_Wgt;
        const void* src = ws + ((size_t)e * M + col0 + r) * (size_t)D + k0 + c * 8;
        cpa16(st + (1 + (p >> 2)) * PLANEB + r * ROWB + c * 16, src);
    }
}

// ---------------- kernel 4: ff1  H = swish(X@Wg+bg) * (X@W1+b1) ----------------
__global__ void __launch_bounds__(256)
k_ff1(const float* __restrict__ bg, const float* __restrict__ b1) {
    extern __shared__ char smem[];
    const int e = blockIdx.z;
    const int base = g_off[e];
    const int cnt = g_off[e + 1] - base;
    const int row0 = blockIdx.x * 128;
    if (row0 >= cnt) return;
    const int col0 = blockIdx.y * 128;
    const int tid = threadIdx.x;
    const int wid = tid >> 5, lane = tid & 31;
    const int warp_m = wid >> 2, warp_n = wid & 3;
    const uint32_t sb = smem_u32(smem);

    int* s_tok = (int*)(smem + 2 * F1_STG);
    if (tid < 128) {
        int gr = row0 + tid;
        s_tok[tid] = (gr < cnt) ? g_slot_tok[base + gr] : -1;
    }
    __syncthreads();

    const uint32_t a_rel = (uint32_t)(((warp_m * 64 + (lane & 15)) * AS + (lane >> 4) * 8) * 2);
    const uint32_t b_rel = (uint32_t)(((warp_n * 32 + (lane & 7) + ((lane >> 4) * 8)) * AS
                                      + ((lane >> 3) & 1) * 8) * 2);

    float cg[4][4][4], cu[4][4][4];
#pragma unroll
    for (int i = 0; i < 4; i++)
#pragma unroll
        for (int j = 0; j < 4; j++)
#pragma unroll
            for (int q = 0; q < 4; q++) { cg[i][j][q] = 0.0f; cu[i][j][q] = 0.0f; }

    ff1_load(sb, 0, 0, tid, s_tok, e, col0);
    CPCOMMIT();

    const int NIT = D / 64;   // 16
    for (int it = 0; it < NIT; it++) {
        if (it + 1 < NIT) {
            ff1_load(sb, (it + 1) & 1, (it + 1) * 64, tid, s_tok, e, col0);
            CPCOMMIT();
            CPWAIT1();
        } else {
            CPWAIT0();
        }
        __syncthreads();
        uint32_t st = sb + (it & 1) * F1_STG;
#pragma unroll
        for (int ks = 0; ks < 4; ks++) {
            const uint32_t kso = (uint32_t)(ks * 32);   // 16 elems = 32 B
            uint32_t ah[4][4];
#pragma unroll
            for (int mt = 0; mt < 4; mt++) {
                uint32_t ad = st + a_rel + (uint32_t)(mt * 16 * ROWB) + kso;
                LDSM4(ah[mt][0], ah[mt][1], ah[mt][2], ah[mt][3], ad);
            }
            uint32_t bgh[4][2], buh[4][2];
#pragma unroll
            for (int nt2 = 0; nt2 < 2; nt2++) {
                uint32_t bd = st + b_rel + (uint32_t)(nt2 * 16 * ROWB) + kso;
                LDSM4(bgh[2*nt2][0], bgh[2*nt2][1], bgh[2*nt2+1][0], bgh[2*nt2+1][1], bd + 1 * PLANEB);
                LDSM4(buh[2*nt2][0], buh[2*nt2][1], buh[2*nt2+1][0], buh[2*nt2+1][1], bd + 2 * PLANEB);
            }
#pragma unroll
            for (int mt = 0; mt < 4; mt++) {
#pragma unroll
                for (int nt = 0; nt < 4; nt++) {
                    MMA16816(cg[mt][nt], ah[mt][0], ah[mt][1], ah[mt][2], ah[mt][3], bgh[nt][0], bgh[nt][1]);
                    MMA16816(cu[mt][nt], ah[mt][0], ah[mt][1], ah[mt][2], ah[mt][3], buh[nt][0], buh[nt][1]);
                }
            }
        }
        __syncthreads();
    }

    // ---- epilogue: swish-gate, write H (fp16) ----
    const float* bg_e = bg + e * M;
    const float* b1_e = b1 + e * M;
    uint32_t* H32 = (uint32_t*)g_H;
#pragma unroll
    for (int mt = 0; mt < 4; mt++) {
#pragma unroll
        for (int nt = 0; nt < 4; nt++) {
            int r_base = row0 + warp_m * 64 + mt * 16 + (lane >> 2);
            int c = col0 + warp_n * 32 + nt * 8 + (lane & 3) * 2;
#pragma unroll
            for (int hh = 0; hh < 2; hh++) {
                int r = r_base + hh * 8;
                if (r < cnt) {
                    float a0 = cg[mt][nt][2*hh]   + bg_e[c];
                    float a1 = cg[mt][nt][2*hh+1] + bg_e[c + 1];
                    float u0 = cu[mt][nt][2*hh]   + b1_e[c];
                    float u1 = cu[mt][nt][2*hh+1] + b1_e[c + 1];
                    float h0 = (a0 / (1.0f + __expf(-a0))) * u0;
                    float h1 = (a1 / (1.0f + __expf(-a1))) * u1;
                    __half2 hp = __floats2half2_rn(h0, h1);
                    H32[((size_t)(base + r) * M + c) >> 1] = *(uint32_t*)&hp;
                }
            }
        }
    }
}

// ff2: stage = 2 planes (A, B), double buffered, K-chunk 64
#define F2_STG  (2 * PLANEB)          // 36864
#define F2_SMEM (2 * F2_STG)          // 73728
#define SPLITK  4

__device__ __forceinline__ void ff2_load(uint32_t sb, int stage, int kabs,
                                         int tid, int base, int cnt,
                                         int row0, int e, int col0) {
    uint32_t st = sb + stage * F2_STG;
    // A: H rows (invalid rows clamped; discarded in epilogue)
#pragma unroll
    for (int p = 0; p < 4; p++) {
        int idx = p * 256 + tid;
        int r = idx >> 3, c = idx & 7;
        int gr = row0 + r;
        if (gr >= cnt) gr = cnt - 1;
        const void* src = g_H + (size_t)(base + gr) * M + kabs + c * 8;
        cpa16(st + r * ROWB + c * 16, src);
    }
    // B: W2 transposed plane [n=D][k=M]
#pragma unroll
    for (int p = 0; p < 4; p++) {
        int idx = p * 256 + tid;
        int r = idx >> 3, c = idx & 7;
        const void* src = g_W2t + ((size_t)e * D + col0 + r) * (size_t)M + kabs + c * 8;
        cpa16(st + PLANEB + r * ROWB + c * 16, src);
    }
}

// ---------------- kernel 5: ff2  Y = H@W2 + b2, weighted combine (split-K) ----
__global__ void __launch_bounds__(256)
k_ff2(const float* __restrict__ b2, float* __restrict__ out) {
    extern __shared__ char smem[];
    const int e = blockIdx.z >> 2;
    const int sk = blockIdx.z & 3;
    const int base = g_off[e];
    const int cnt = g_off[e + 1] - base;
    const int row0 = blockIdx.x * 128;
    if (row0 >= cnt) return;
    const int col0 = blockIdx.y * 128;
    const int kb = sk * (M / SPLITK);
    const int tid = threadIdx.x;
    const int wid = tid >> 5, lane = tid & 31;
    const int warp_m = wid >> 2, warp_n = wid & 3;
    const uint32_t sb = smem_u32(smem);

    const uint32_t a_rel = (uint32_t)(((warp_m * 64 + (lane & 15)) * AS + (lane >> 4) * 8) * 2);
    const uint32_t b_rel = (uint32_t)(((warp_n * 32 + (lane & 7) + ((lane >> 4) * 8)) * AS
                                      + ((lane >> 3) & 1) * 8) * 2);

    float cc[4][4][4];
#pragma unroll
    for (int i = 0; i < 4; i++)
#pragma unroll
        for (int j = 0; j < 4; j++)
#pragma unroll
            for (int q = 0; q < 4; q++) cc[i][j][q] = 0.0f;

    ff2_load(sb, 0, kb, tid, base, cnt, row0, e, col0);
    CPCOMMIT();

    const int NIT = (M / SPLITK) / 64;   // 16
    for (int it = 0; it < NIT; it++) {
        if (it + 1 < NIT) {
            ff2_load(sb, (it + 1) & 1, kb + (it + 1) * 64, tid, base, cnt, row0, e, col0);
            CPCOMMIT();
            CPWAIT1();
        } else {
            CPWAIT0();
        }
        __syncthreads();
        uint32_t st = sb + (it & 1) * F2_STG;
#pragma unroll
        for (int ks = 0; ks < 4; ks++) {
            const uint32_t kso = (uint32_t)(ks * 32);
            uint32_t ah[4][4];
#pragma unroll
            for (int mt = 0; mt < 4; mt++) {
                uint32_t ad = st + a_rel + (uint32_t)(mt * 16 * ROWB) + kso;
                LDSM4(ah[mt][0], ah[mt][1], ah[mt][2], ah[mt][3], ad);
            }
            uint32_t bh[4][2];
#pragma unroll
            for (int nt2 = 0; nt2 < 2; nt2++) {
                uint32_t bd = st + b_rel + (uint32_t)(nt2 * 16 * ROWB) + kso;
                LDSM4(bh[2*nt2][0], bh[2*nt2][1], bh[2*nt2+1][0], bh[2*nt2+1][1], bd + PLANEB);
            }
#pragma unroll
            for (int mt = 0; mt < 4; mt++) {
#pragma unroll
                for (int nt = 0; nt < 4; nt++) {
                    MMA16816(cc[mt][nt], ah[mt][0], ah[mt][1], ah[mt][2], ah[mt][3], bh[nt][0], bh[nt][1]);
                }
            }
        }
        __syncthreads();
    }

    // ---- epilogue: (bias on split 0) + weighted atomic combine ----
    const float* b2_e = b2 + e * D;
#pragma unroll
    for (int mt = 0; mt < 4; mt++) {
#pragma unroll
        for (int nt = 0; nt < 4; nt++) {
            int r_base = row0 + warp_m * 64 + mt * 16 + (lane >> 2);
            int c = col0 + warp_n * 32 + nt * 8 + (lane & 3) * 2;
            float bb0 = (sk == 0) ? b2_e[c]     : 0.0f;
            float bb1 = (sk == 0) ? b2_e[c + 1] : 0.0f;
#pragma unroll
            for (int hh = 0; hh < 2; hh++) {
                int r = r_base + hh * 8;
                if (r < cnt) {
                    int slot = base + r;
                    int tok = g_slot_tok[slot];
                    float w = g_slot_w[slot];
                    float y0 = cc[mt][nt][2*hh]   + bb0;
                    float y1 = cc[mt][nt][2*hh+1] + bb1;
                    float* op = out + (size_t)tok * D + c;
                    atomicAdd(op,     w * y0);
                    atomicAdd(op + 1, w * y1);
                }
            }
        }
    }
}

// ---------------- launch ----------------
extern "C" void kernel_launch(void* const* d_in, const int* in_sizes, int n_in,
                              void* d_out, int out_size) {
    const float* x     = (const float*)d_in[0];
    const float* Wgate = (const float*)d_in[1];
    const float* bgate = (const float*)d_in[2];
    const float* Wg    = (const float*)d_in[3];
    const float* bg    = (const float*)d_in[4];
    const float* W1    = (const float*)d_in[5];
    const float* b1    = (const float*)d_in[6];
    const float* W2    = (const float*)d_in[7];
    const float* b2    = (const float*)d_in[8];
    float* out = (float*)d_out;

    cudaFuncSetAttribute(k_ff1, cudaFuncAttributeMaxDynamicSharedMemorySize, F1_SMEM);
    cudaFuncSetAttribute(k_ff2, cudaFuncAttributeMaxDynamicSharedMemorySize, F2_SMEM);

    k_init<<<(S * D + 511) / 512, 512>>>(out);
    k_gate<<<S / 8, 256>>>(x, Wgate, bgate);
    k_offsets<<<1, 32>>>();
    k_scatter<<<(S + 255) / 256, 256>>>();

    // prep: fp16 conversion (+ weight transpose); plane selected device-side
    k_xcvt<<<(S * D / 2 + 255) / 256, 256>>>(x);
    dim3 tb(32, 8);
    k_tcvt<<<dim3(M / 32, D / 64, E), tb>>>(Wg, 0, D, M);
    k_tcvt<<<dim3(M / 32, D / 64, E), tb>>>(W1, 1, D, M);
    k_tcvt<<<dim3(D / 32, M / 64, E), tb>>>(W2, 2, M, D);

    dim3 g1(NSLOT / 128, M / 128, E);          // (32, 32, 8)
    k_ff1<<<g1, 256, F1_SMEM>>>(bg, b1);
    dim3 g2(NSLOT / 128, D / 128, E * SPLITK); // (32, 8, 32)
    k_ff2<<<g2, 256, F2_SMEM>>>(b2, out);
}